// round 14
// baseline (speedup 1.0000x reference)
#include <cuda_runtime.h>
#include <cuda_fp16.h>
#include <stdint.h>

#define R_NODES   256
#define N_STEPS   512
#define M_SAMP    512
#define OUT_DIM   10
#define LUT_WORDS 8192            // 2^18 bits / 32
#define NPC       4               // samples per CTA
#define N_CTA     (M_SAMP / NPC)  // 128 CTAs -> 1 per SM
#define THREADS   512             // 16 warps: warp w owns nodes [16w, 16w+16)
#define RB_STRIDE 264             // halfs per row: word banks (4g+tg) distinct
#define MAGIC_F   8388608.0f      // 2^23: accumulator mantissa low 23 bits == integer sum

// Scratch: __device__ globals (no allocation allowed)
__device__ unsigned g_lut_bits[R_NODES * LUT_WORDS]; // 8 MB bit-packed LUT

// ---------------------------------------------------------------------------
// Pack LUT (flat): word w, bit b = lut[w*32 + b]. MLP=32 load stage then ballots.
// ---------------------------------------------------------------------------
__global__ void pack_lut_kernel(const int* __restrict__ lut) {
    const int warp_g = (blockIdx.x * blockDim.x + threadIdx.x) >> 5;
    const int lane   = threadIdx.x & 31;
    const int w0     = warp_g * 32;
    const unsigned* src = (const unsigned*)lut;
    unsigned v[32];
    #pragma unroll
    for (int i = 0; i < 32; i++)
        v[i] = src[(size_t)(w0 + i) * 32 + lane];
    unsigned myw = 0;
    #pragma unroll
    for (int i = 0; i < 32; i++) {
        unsigned b = __ballot_sync(0xFFFFFFFFu, v[i] & 1u);
        if (i == lane) myw = b;
    }
    g_lut_bits[w0 + lane] = myw;
}

// ---------------------------------------------------------------------------
// m16n8k16 fp16 MMA, fp32 accumulate (exact for our integer ranges)
// ---------------------------------------------------------------------------
__device__ __forceinline__ void mma16816(float* d, const unsigned* a, unsigned b0, unsigned b1) {
    asm volatile(
        "mma.sync.aligned.m16n8k16.row.col.f32.f16.f16.f32 "
        "{%0,%1,%2,%3}, {%4,%5,%6,%7}, {%8,%9}, {%0,%1,%2,%3};\n"
        : "+f"(d[0]), "+f"(d[1]), "+f"(d[2]), "+f"(d[3])
        : "r"(a[0]), "r"(a[1]), "r"(a[2]), "r"(a[3]), "r"(b0), "r"(b1));
}

// ---------------------------------------------------------------------------
// Reservoir kernel: 128 CTAs x 512 threads (16 warps), CTA b owns samples
// [4b, 4b+4). Warp w owns nodes [16w, 16w+16): one m16n8k16 tile, A in 64
// regs. 4 warps/SMSP hide MMA-chain and L2-gather latency (fix for the
// occ=12.5% latency-bound profile). B rows 4-7 are permanently zero (D cols
// 4-7 unused) -> no mirror stores. Lanes tg<2 gather 4 LUT words each.
// ---------------------------------------------------------------------------
__global__ void __launch_bounds__(THREADS, 1)
reservoir_kernel(const int* __restrict__ x,
                 const int* __restrict__ input_nodes,
                 const int* __restrict__ Wres,
                 const int* __restrict__ primes,
                 const int* __restrict__ init_res,
                 const float* __restrict__ readout_W,
                 const float* __restrict__ readout_b,
                 float* __restrict__ out)
{
    __shared__ __half rb[2][8][RB_STRIDE];       // double-buffered; rows 4-7 zero
    __shared__ unsigned s_x[NPC][N_STEPS];       // packed inputs, bit i = feature i
    __shared__ short s_inp[R_NODES];
    __shared__ int s_innodes[32];
    __shared__ unsigned short s_ph[R_NODES];
    __shared__ float s_W[OUT_DIM * R_NODES];

    const int tid  = threadIdx.x;
    const int wid  = tid >> 5;
    const int lane = tid & 31;
    const int g    = lane >> 2;
    const int tg   = lane & 3;
    const int mbase = blockIdx.x * NPC;
    const __half ONE  = __ushort_as_half(0x3C00);
    const __half ZERO = __ushort_as_half(0x0000);

    // ---- tables ----
    if (tid < R_NODES) {
        s_inp[tid] = -1;
        s_ph[tid]  = __half_as_ushort(__int2half_rn(primes[tid]));
    }
    for (int i = tid; i < OUT_DIM * R_NODES; i += THREADS) s_W[i] = readout_W[i];
    __syncthreads();
    if (tid < 32) {
        int nn = input_nodes[tid];
        s_innodes[tid] = nn;
        s_inp[nn] = (short)tid;
    }

    // ---- pack this CTA's x slice: NPC*512 = 2048 words, 32 ints each ----
    for (int w = tid; w < NPC * N_STEPS; w += THREADS) {
        int s = w >> 9;
        int t = w & (N_STEPS - 1);
        const uint4* p = (const uint4*)(x + ((size_t)(mbase + s) * N_STEPS + t) * 32);
        unsigned word = 0;
        #pragma unroll
        for (int j = 0; j < 8; j++) {
            uint4 v = p[j];
            word |= (v.x & 1u) << (4 * j + 0);
            word |= (v.y & 1u) << (4 * j + 1);
            word |= (v.z & 1u) << (4 * j + 2);
            word |= (v.w & 1u) << (4 * j + 3);
        }
        s_x[s][t] = word;
    }

    // ---- A fragments: warp w -> 16 nodes, 64 regs ----
    unsigned A[16][4];
    const int node_base = wid * 16;
    #pragma unroll
    for (int kt = 0; kt < 16; kt++) {
        #pragma unroll
        for (int r = 0; r < 4; r++) {
            int row = node_base + g + ((r & 1) ? 8 : 0);
            int k0  = kt * 16 + tg * 2 + ((r & 2) ? 8 : 0);
            unsigned h0 = Wres[row * 256 + k0]     ? (unsigned)s_ph[k0]     : 0u;
            unsigned h1 = Wres[row * 256 + k0 + 1] ? (unsigned)s_ph[k0 + 1] : 0u;
            A[kt][r] = h0 | (h1 << 16);
        }
    }

    // ---- init: rows 0-3 = init_res (then x_0); rows 4-7 = zero forever ----
    if (tid < R_NODES) {
        __half v = init_res[tid] ? ONE : ZERO;
        #pragma unroll
        for (int s = 0; s < NPC; s++) rb[0][s][tid] = v;
        #pragma unroll
        for (int s = NPC; s < 8; s++) { rb[0][s][tid] = ZERO; rb[1][s][tid] = ZERO; }
    } else if (tid < R_NODES + 64) {             // pad halfs 256..263 of all rows
        int q = tid - R_NODES;                   // 0..63 -> row q>>3, pad idx q&7
        rb[0][q >> 3][256 + (q & 7)] = ZERO;
        rb[1][q >> 3][256 + (q & 7)] = ZERO;
    }
    __syncthreads();
    if (tid < NPC * 32) {
        int s = tid >> 5, i = tid & 31;
        rb[0][s][s_innodes[i]] = ((s_x[s][0] >> i) & 1u) ? ONE : ZERO;
    }
    __syncthreads();

    // ---- per-lane gather constants (gatherers: tg < 2) ----
    const bool gatherer = (tg < 2);
    const int n0 = node_base + g;                // lane's two nodes
    const int n1 = n0 + 8;
    const int sA = tg * 2;                       // lane's two samples (tg<2): sA, sA+1
    const bool i0 = (s_inp[n0] >= 0);
    const bool i1 = (s_inp[n1] >= 0);
    const unsigned* lp0 = g_lut_bits + (size_t)n0 * LUT_WORDS;
    const unsigned* lp1 = g_lut_bits + (size_t)n1 * LUT_WORDS;
    const int xs = tid >> 5, xi = tid & 31;      // x-overwrite role (threads < 128)
    const int xnode = (tid < NPC * 32) ? s_innodes[xi] : 0;

    // ---- 512 sequential steps, one barrier per step ----
    for (int t = 0; t < N_STEPS; t++) {
        const int p = t & 1;
        const bool last = (t == N_STEPS - 1);
        const __half (*cur)[RB_STRIDE] = rb[p];
        __half (*nxt)[RB_STRIDE] = rb[p ^ 1];

        unsigned xw = 0;
        if (!last && tid < NPC * 32) xw = s_x[xs][t + 1];

        // 16-HMMA chain, 4-split accumulators (chunk 0 carries magic offset)
        float d[4][4];
        #pragma unroll
        for (int c = 0; c < 4; c++)
            #pragma unroll
            for (int e = 0; e < 4; e++) d[c][e] = (c == 0) ? MAGIC_F : 0.0f;
        #pragma unroll
        for (int kt = 0; kt < 16; kt++) {
            unsigned b0 = *(const unsigned*)&cur[g][kt * 16 + tg * 2];
            unsigned b1 = *(const unsigned*)&cur[g][kt * 16 + tg * 2 + 8];
            mma16816(d[kt & 3], A[kt], b0, b1);
        }

        if (gatherer) {
            const bool d0 = last || !i0;
            const bool d1 = last || !i1;
            unsigned u[4], w[4];
            #pragma unroll
            for (int e = 0; e < 4; e++) {
                float tot = (d[0][e] + d[1][e]) + (d[2][e] + d[3][e]);
                u[e] = __float_as_uint(tot) & 0x7FFFFFu;
            }
            if (d0) { w[0] = __ldg(&lp0[u[0] >> 5]); w[1] = __ldg(&lp0[u[1] >> 5]); }
            if (d1) { w[2] = __ldg(&lp1[u[2] >> 5]); w[3] = __ldg(&lp1[u[3] >> 5]); }
            #pragma unroll
            for (int e = 0; e < 4; e++) {
                bool de = (e & 2) ? d1 : d0;
                if (de) {
                    int node = (e & 2) ? n1 : n0;
                    int samp = sA + (e & 1);
                    nxt[samp][node] = ((w[e] >> (u[e] & 31)) & 1u) ? ONE : ZERO;
                }
            }
        }

        // x_{t+1} into input nodes of next buffer (threads 0..127)
        if (!last && tid < NPC * 32)
            nxt[xs][xnode] = ((xw >> xi) & 1u) ? ONE : ZERO;

        __syncthreads();
    }

    // ---- readout: warps 0-3, warp w -> sample w; final state in rb[0] ----
    if (wid < NPC) {
        float acc[OUT_DIM];
        #pragma unroll
        for (int o = 0; o < OUT_DIM; o++) acc[o] = 0.0f;
        #pragma unroll
        for (int kk = 0; kk < 8; kk++) {
            int k = lane + kk * 32;
            float rv = __half2float(rb[0][wid][k]);
            #pragma unroll
            for (int o = 0; o < OUT_DIM; o++)
                acc[o] += rv * s_W[o * R_NODES + k];
        }
        #pragma unroll
        for (int o = 0; o < OUT_DIM; o++) {
            #pragma unroll
            for (int off = 16; off; off >>= 1)
                acc[o] += __shfl_xor_sync(0xFFFFFFFFu, acc[o], off);
        }
        if (lane == 0) {
            #pragma unroll
            for (int o = 0; o < OUT_DIM; o++)
                out[(mbase + wid) * OUT_DIM + o] = acc[o] + readout_b[o];
        }
    }
}

// ---------------------------------------------------------------------------
// kernel_launch. Inputs: x, input_nodes, lut, W_res, primes, init_res,
// readout_W, readout_b (bool arrays delivered as int32). Two launches:
// pack_lut then reservoir (x packing fused into the reservoir prologue).
// ---------------------------------------------------------------------------
extern "C" void kernel_launch(void* const* d_in, const int* in_sizes, int n_in,
                              void* d_out, int out_size) {
    const int*   x        = (const int*)d_in[0];
    const int*   in_nodes = (const int*)d_in[1];
    const int*   lut      = (const int*)d_in[2];
    const int*   Wres     = (const int*)d_in[3];
    const int*   primes   = (const int*)d_in[4];
    const int*   init_res = (const int*)d_in[5];
    const float* rW       = (const float*)d_in[6];
    const float* rb       = (const float*)d_in[7];
    float*       out      = (float*)d_out;

    pack_lut_kernel<<<(R_NODES * LUT_WORDS) / (32 * 8), 256>>>(lut);
    reservoir_kernel<<<N_CTA, THREADS>>>(x, in_nodes, Wres, primes, init_res, rW, rb, out);
}

// round 16
// speedup vs baseline: 1.0229x; 1.0229x over previous
#include <cuda_runtime.h>
#include <cuda_fp16.h>
#include <stdint.h>

#define R_NODES   256
#define N_STEPS   512
#define M_SAMP    512
#define OUT_DIM   10
#define LUT_WORDS 8192            // 2^18 bits / 32
#define NPC       4               // samples per CTA
#define N_CTA     (M_SAMP / NPC)  // 128 CTAs -> 1 per SM
#define MAGIC_F   8388608.0f      // 2^23: accumulator mantissa low 23 bits == integer sum

// Scratch: __device__ globals (no allocation allowed)
__device__ unsigned g_lut_bits[R_NODES * LUT_WORDS]; // 8 MB bit-packed LUT

// ---------------------------------------------------------------------------
// Pack LUT (flat): word w, bit b = lut[w*32 + b]. MLP=32 load stage then ballots.
// ---------------------------------------------------------------------------
__global__ void pack_lut_kernel(const int* __restrict__ lut) {
    const int warp_g = (blockIdx.x * blockDim.x + threadIdx.x) >> 5;
    const int lane   = threadIdx.x & 31;
    const int w0     = warp_g * 32;
    const unsigned* src = (const unsigned*)lut;
    unsigned v[32];
    #pragma unroll
    for (int i = 0; i < 32; i++)
        v[i] = src[(size_t)(w0 + i) * 32 + lane];
    unsigned myw = 0;
    #pragma unroll
    for (int i = 0; i < 32; i++) {
        unsigned b = __ballot_sync(0xFFFFFFFFu, v[i] & 1u);
        if (i == lane) myw = b;
    }
    g_lut_bits[w0 + lane] = myw;
}

// ---------------------------------------------------------------------------
// m16n8k16 fp16 MMA, fp32 accumulate (exact for our integer ranges)
// ---------------------------------------------------------------------------
__device__ __forceinline__ void mma16816(float* d, const unsigned* a, unsigned b0, unsigned b1) {
    asm volatile(
        "mma.sync.aligned.m16n8k16.row.col.f32.f16.f16.f32 "
        "{%0,%1,%2,%3}, {%4,%5,%6,%7}, {%8,%9}, {%0,%1,%2,%3};\n"
        : "+f"(d[0]), "+f"(d[1]), "+f"(d[2]), "+f"(d[3])
        : "r"(a[0]), "r"(a[1]), "r"(a[2]), "r"(a[3]), "r"(b0), "r"(b1));
}

// ldmatrix x2 transposed: B fragments (b0 = rows k0..k7, b1 = rows k8..k15)
__device__ __forceinline__ void ldsm_x2_t(unsigned& b0, unsigned& b1, uint32_t addr) {
    asm volatile("ldmatrix.sync.aligned.m8n8.x2.trans.shared.b16 {%0,%1}, [%2];"
                 : "=r"(b0), "=r"(b1) : "r"(addr));
}

__device__ __forceinline__ uint32_t smem_u32(const void* p) {
    uint32_t a;
    asm("{ .reg .u64 t; cvta.to.shared.u64 t, %1; cvt.u32.u64 %0, t; }" : "=r"(a) : "l"(p));
    return a;
}

// ---------------------------------------------------------------------------
// Reservoir kernel: 128 CTAs x 256 threads, CTA b owns samples [4b, 4b+4).
// State stored TRANSPOSED: st[buf][node][sample] fp16 (16B rows; cols 4-7
// permanently zero). B fragments come from ldmatrix.x2.trans (16 per warp per
// step, conflict-free). Warp w owns nodes [32w, 32w+32): A in 128 regs.
// Gatherer lanes (tg<2) do 8 LUT loads and 4 vectorized u32 state stores.
// ---------------------------------------------------------------------------
__global__ void __launch_bounds__(256, 1)
reservoir_kernel(const int* __restrict__ x,
                 const int* __restrict__ input_nodes,
                 const int* __restrict__ Wres,
                 const int* __restrict__ primes,
                 const int* __restrict__ init_res,
                 const float* __restrict__ readout_W,
                 const float* __restrict__ readout_b,
                 float* __restrict__ out)
{
    __shared__ __half st[2][R_NODES][8];         // [buf][node][sample], cols 4-7 zero
    __shared__ unsigned s_x[NPC][N_STEPS];       // packed inputs, bit i = feature i
    __shared__ short s_inp[R_NODES];
    __shared__ int s_innodes[32];
    __shared__ unsigned short s_ph[R_NODES];
    __shared__ float s_W[OUT_DIM * R_NODES];

    const int tid  = threadIdx.x;
    const int wid  = tid >> 5;
    const int lane = tid & 31;
    const int g    = lane >> 2;
    const int tg   = lane & 3;
    const int mbase = blockIdx.x * NPC;
    const __half ONE  = __ushort_as_half(0x3C00);
    const __half ZERO = __ushort_as_half(0x0000);

    // ---- tables ----
    s_inp[tid] = -1;
    s_ph[tid]  = __half_as_ushort(__int2half_rn(primes[tid]));
    for (int i = tid; i < OUT_DIM * R_NODES; i += 256) s_W[i] = readout_W[i];
    __syncthreads();
    if (tid < 32) {
        int nn = input_nodes[tid];
        s_innodes[tid] = nn;
        s_inp[nn] = (short)tid;
    }

    // ---- pack this CTA's x slice: NPC*512 = 2048 words, 32 ints each ----
    for (int w = tid; w < NPC * N_STEPS; w += 256) {
        int s = w >> 9;
        int t = w & (N_STEPS - 1);
        const uint4* p = (const uint4*)(x + ((size_t)(mbase + s) * N_STEPS + t) * 32);
        unsigned word = 0;
        #pragma unroll
        for (int j = 0; j < 8; j++) {
            uint4 v = p[j];
            word |= (v.x & 1u) << (4 * j + 0);
            word |= (v.y & 1u) << (4 * j + 1);
            word |= (v.z & 1u) << (4 * j + 2);
            word |= (v.w & 1u) << (4 * j + 3);
        }
        s_x[s][t] = word;
    }

    // ---- A fragments (Wp = Wres ? prime : 0), register-resident ----
    unsigned A[16][2][4];
    const int node_base = wid * 32;
    #pragma unroll
    for (int kt = 0; kt < 16; kt++) {
        #pragma unroll
        for (int mt = 0; mt < 2; mt++) {
            #pragma unroll
            for (int r = 0; r < 4; r++) {
                int row = node_base + mt * 16 + g + ((r & 1) ? 8 : 0);
                int k0  = kt * 16 + tg * 2 + ((r & 2) ? 8 : 0);
                unsigned h0 = Wres[row * 256 + k0]     ? (unsigned)s_ph[k0]     : 0u;
                unsigned h1 = Wres[row * 256 + k0 + 1] ? (unsigned)s_ph[k0 + 1] : 0u;
                A[kt][mt][r] = h0 | (h1 << 16);
            }
        }
    }

    // ---- init: cols 0-3 = init_res, cols 4-7 = zero forever (both buffers) ----
    {
        __half v = init_res[tid] ? ONE : ZERO;
        #pragma unroll
        for (int s = 0; s < NPC; s++) { st[0][tid][s] = v; st[1][tid][s] = v; }
        #pragma unroll
        for (int s = NPC; s < 8; s++) { st[0][tid][s] = ZERO; st[1][tid][s] = ZERO; }
    }
    __syncthreads();
    if (tid < NPC * 32) {
        int s = tid >> 5, i = tid & 31;
        st[0][s_innodes[i]][s] = ((s_x[s][0] >> i) & 1u) ? ONE : ZERO;
    }
    __syncthreads();

    // ---- per-lane constants ----
    const bool gatherer = (tg < 2);
    const int sA = tg * 2;                       // gatherer's two samples (tg<2)
    const unsigned* lp[2][2];
    int nodes[2][2];
    bool is_inp[2][2];
    #pragma unroll
    for (int mt = 0; mt < 2; mt++)
        #pragma unroll
        for (int h = 0; h < 2; h++) {
            int n = node_base + mt * 16 + g + h * 8;
            nodes[mt][h]  = n;
            lp[mt][h]     = g_lut_bits + (size_t)n * LUT_WORDS;
            is_inp[mt][h] = (s_inp[n] >= 0);
        }
    const int xs = tid >> 5, xi = tid & 31;      // x-overwrite role (threads < 128)
    const int xnode = (tid < NPC * 32) ? s_innodes[xi] : 0;

    // ldmatrix row base addresses per buffer: lane (l&15) supplies row kt*16+(l&15)
    const uint32_t row0 = smem_u32(&st[0][0][0]) + (unsigned)(lane & 15) * 16;
    const uint32_t row1 = smem_u32(&st[1][0][0]) + (unsigned)(lane & 15) * 16;

    // ---- 512 sequential steps, one barrier per step ----
    for (int t = 0; t < N_STEPS; t++) {
        const int p = t & 1;
        const bool last = (t == N_STEPS - 1);
        const uint32_t rbase = p ? row1 : row0;
        __half (*nxt)[8] = st[p ^ 1];

        unsigned xw = 0;
        if (!last && tid < NPC * 32) xw = s_x[xs][t + 1];

        // 32-HMMA step (two m-tiles), B via ldmatrix, 4-split accumulators
        float d0[4][4], d1[4][4];
        #pragma unroll
        for (int c = 0; c < 4; c++)
            #pragma unroll
            for (int e = 0; e < 4; e++) {
                d0[c][e] = (c == 0) ? MAGIC_F : 0.0f;
                d1[c][e] = (c == 0) ? MAGIC_F : 0.0f;
            }
        #pragma unroll
        for (int kt = 0; kt < 16; kt++) {
            unsigned b0, b1;
            ldsm_x2_t(b0, b1, rbase + (unsigned)kt * 256);
            mma16816(d0[kt & 3], A[kt][0], b0, b1);
            mma16816(d1[kt & 3], A[kt][1], b0, b1);
        }

        if (gatherer) {
            unsigned u[2][4], w[2][4];
            #pragma unroll
            for (int e = 0; e < 4; e++) {
                float t0 = (d0[0][e] + d0[1][e]) + (d0[2][e] + d0[3][e]);
                float t1 = (d1[0][e] + d1[1][e]) + (d1[2][e] + d1[3][e]);
                u[0][e] = __float_as_uint(t0) & 0x7FFFFFu;
                u[1][e] = __float_as_uint(t1) & 0x7FFFFFu;
            }
            #pragma unroll
            for (int mt = 0; mt < 2; mt++)
                #pragma unroll
                for (int e = 0; e < 4; e++)
                    if (last || !is_inp[mt][e >> 1])
                        w[mt][e] = __ldg(&lp[mt][e >> 1][u[mt][e] >> 5]);
            #pragma unroll
            for (int mt = 0; mt < 2; mt++)
                #pragma unroll
                for (int h = 0; h < 2; h++)
                    if (last || !is_inp[mt][h]) {
                        unsigned bl = (w[mt][2 * h]     >> (u[mt][2 * h]     & 31)) & 1u;
                        unsigned bh = (w[mt][2 * h + 1] >> (u[mt][2 * h + 1] & 31)) & 1u;
                        unsigned val = (bl ? 0x3C00u : 0u) | (bh ? 0x3C000000u : 0u);
                        *(unsigned*)&nxt[nodes[mt][h]][sA] = val;   // samples sA, sA+1
                    }
        }

        // x_{t+1} into input nodes of next buffer (threads 0..127)
        if (!last && tid < NPC * 32)
            nxt[xnode][xs] = ((xw >> xi) & 1u) ? ONE : ZERO;

        __syncthreads();
    }

    // ---- readout: warps 0-3, warp w -> sample w; final state in st[0] ----
    if (wid < NPC) {
        float acc[OUT_DIM];
        #pragma unroll
        for (int o = 0; o < OUT_DIM; o++) acc[o] = 0.0f;
        #pragma unroll
        for (int kk = 0; kk < 8; kk++) {
            int k = lane + kk * 32;
            float rv = __half2float(st[0][k][wid]);
            #pragma unroll
            for (int o = 0; o < OUT_DIM; o++)
                acc[o] += rv * s_W[o * R_NODES + k];
        }
        #pragma unroll
        for (int o = 0; o < OUT_DIM; o++) {
            #pragma unroll
            for (int off = 16; off; off >>= 1)
                acc[o] += __shfl_xor_sync(0xFFFFFFFFu, acc[o], off);
        }
        if (lane == 0) {
            #pragma unroll
            for (int o = 0; o < OUT_DIM; o++)
                out[(mbase + wid) * OUT_DIM + o] = acc[o] + readout_b[o];
        }
    }
}

// ---------------------------------------------------------------------------
// kernel_launch. Inputs: x, input_nodes, lut, W_res, primes, init_res,
// readout_W, readout_b (bool arrays delivered as int32). Two launches:
// pack_lut then reservoir (x packing fused into the reservoir prologue).
// ---------------------------------------------------------------------------
extern "C" void kernel_launch(void* const* d_in, const int* in_sizes, int n_in,
                              void* d_out, int out_size) {
    const int*   x        = (const int*)d_in[0];
    const int*   in_nodes = (const int*)d_in[1];
    const int*   lut      = (const int*)d_in[2];
    const int*   Wres     = (const int*)d_in[3];
    const int*   primes   = (const int*)d_in[4];
    const int*   init_res = (const int*)d_in[5];
    const float* rW       = (const float*)d_in[6];
    const float* rb       = (const float*)d_in[7];
    float*       out      = (float*)d_out;

    pack_lut_kernel<<<(R_NODES * LUT_WORDS) / (32 * 8), 256>>>(lut);
    reservoir_kernel<<<N_CTA, 256>>>(x, in_nodes, Wres, primes, init_res, rW, rb, out);
}